// round 4
// baseline (speedup 1.0000x reference)
#include <cuda_runtime.h>
#include <cstdint>

#define BB   4
#define CIN  32
#define HH   320
#define WW   640
#define HWC  (HH*WW)
#define NPIX (BB*HWC)
#define CCAT 128
#define SFC  32

// scratch (planar NCHW everywhere)
__device__ float g_xn[(size_t)NPIX * CIN];
__device__ float g_feats[(size_t)NPIX * CCAT];
__device__ float g_h[(size_t)NPIX * SFC];
__device__ float g_stats[512];  // [0:128) sum feats, [128:256) sumsq feats, [256:288) sum h, [288:320) sumsq h
__device__ float g_bn[512];     // [0:128) scale feats, [128:256) shift feats, [256:288) scale h, [288:320) shift h

__global__ void k_zero() { g_stats[threadIdx.x] = 0.f; }

// L2-normalize per pixel across channels (planar in, planar out)
__global__ void k_norm(const float* __restrict__ x) {
    int idx = blockIdx.x * 256 + threadIdx.x;
    int b = idx / HWC, p = idx - b * HWC;
    const float* xp = x + (size_t)b * CIN * HWC + p;
    float* op = g_xn + (size_t)b * CIN * HWC + p;
    float v[CIN];
    float ss = 0.f;
#pragma unroll
    for (int c = 0; c < CIN; c++) { v[c] = xp[(size_t)c * HWC]; ss += v[c] * v[c]; }
    float rn = 1.f / fmaxf(sqrtf(ss), 1e-12f);
#pragma unroll
    for (int c = 0; c < CIN; c++) op[(size_t)c * HWC] = v[c] * rn;
}

// affinity (4 dilations x 8 neighbors, unfold order) + per-branch 1x1 (8->32), planar out
__global__ void k_aff(const float* __restrict__ w1, const float* __restrict__ w2,
                      const float* __restrict__ w3, const float* __restrict__ w4) {
    __shared__ float s_w[4 * 256];   // [di][o*8+k], same layout as source
    {
        int tid = threadIdx.x;
        const float* ws[4] = {w1, w2, w3, w4};
        for (int di = 0; di < 4; di++) s_w[di * 256 + tid] = ws[di][tid];
    }
    __syncthreads();

    int idx = blockIdx.x * 256 + threadIdx.x;
    int b = idx / HWC, p = idx - b * HWC;
    int y = p / WW, xx = p - y * WW;
    const float* xb = g_xn + (size_t)b * CIN * HWC;

    float cv[CIN];
#pragma unroll
    for (int c = 0; c < CIN; c++) cv[c] = xb[(size_t)c * HWC + p];

#pragma unroll 1
    for (int di = 0; di < 4; di++) {
        int d = 1 << di;
        float a[8];
        int kk = 0;
#pragma unroll
        for (int iy = -1; iy <= 1; iy++) {
#pragma unroll
            for (int jx = -1; jx <= 1; jx++) {
                if (iy == 0 && jx == 0) continue;
                int ny = y + iy * d, nx = xx + jx * d;
                float dot = 0.f;
                if ((unsigned)ny < HH && (unsigned)nx < WW) {
                    int np = ny * WW + nx;
#pragma unroll
                    for (int c = 0; c < CIN; c++) dot += cv[c] * xb[(size_t)c * HWC + np];
                }
                a[kk++] = fmaxf(dot, 0.f);
            }
        }
        // h[o] = sum_k a[k] * w[o,k]  -> planar channel (di*32+o)
        float* fo = g_feats + ((size_t)b * CCAT + di * 32) * HWC + p;
        const float* wd = &s_w[di * 256];
#pragma unroll
        for (int o = 0; o < 32; o++) {
            float s = 0.f;
#pragma unroll
            for (int k = 0; k < 8; k++) s += a[k] * wd[o * 8 + k];
            fo[(size_t)o * HWC] = s;
        }
    }
}

// per-channel sum & sumsq over planar buffer. which: 0 = g_feats(128ch), 1 = g_h(32ch)
__global__ void k_stats(int which, int nch, int statoff) {
    const float* buf = which ? g_h : g_feats;
    int c = blockIdx.x;
    int slice = blockIdx.y;      // 25 slices of 32768 elements over 4*HWC
    int tid = threadIdx.x;
    float s = 0.f, q = 0.f;
    int e0 = slice * 32768;
    for (int e = e0 + tid; e < e0 + 32768; e += 256) {
        int b = e / HWC, p = e - b * HWC;
        float v = buf[((size_t)b * nch + c) * HWC + p];
        s += v; q += v * v;
    }
    __shared__ float ss[256], sq[256];
    ss[tid] = s; sq[tid] = q;
    __syncthreads();
    for (int off = 128; off > 0; off >>= 1) {
        if (tid < off) { ss[tid] += ss[tid + off]; sq[tid] += sq[tid + off]; }
        __syncthreads();
    }
    if (tid == 0) {
        atomicAdd(&g_stats[statoff + c], ss[0]);
        atomicAdd(&g_stats[statoff + nch + c], sq[0]);
    }
}

__global__ void k_bnfin128(const float* __restrict__ g1, const float* __restrict__ b1,
                           const float* __restrict__ g2, const float* __restrict__ b2,
                           const float* __restrict__ g3, const float* __restrict__ b3,
                           const float* __restrict__ g4, const float* __restrict__ b4) {
    int c = threadIdx.x;
    float inv = 1.0f / (float)NPIX;
    float mean = g_stats[c] * inv;
    float var = g_stats[128 + c] * inv - mean * mean;
    int di = c >> 5, o = c & 31;
    const float* gs[4] = {g1, g2, g3, g4};
    const float* bs[4] = {b1, b2, b3, b4};
    float sc = gs[di][o] * rsqrtf(fmaxf(var, 0.f) + 1e-5f);
    g_bn[c] = sc;
    g_bn[128 + c] = bs[di][o] - mean * sc;
}

__global__ void k_bnfin32(const float* __restrict__ gl, const float* __restrict__ bl) {
    int o = threadIdx.x;
    float inv = 1.0f / (float)NPIX;
    float mean = g_stats[256 + o] * inv;
    float var = g_stats[288 + o] * inv - mean * mean;
    float sc = gl[o] * rsqrtf(fmaxf(var, 0.f) + 1e-5f);
    g_bn[256 + o] = sc;
    g_bn[288 + o] = bl[o] - mean * sc;
}

// in-place BN + ReLU over planar buffer
__global__ void k_bnapply(int which, int nch, int scoff, int shoff) {
    float* buf = which ? g_h : g_feats;
    size_t idx = (size_t)blockIdx.x * 256 + threadIdx.x;
    int c = (int)((idx / HWC) % nch);
    float v = buf[idx];
    buf[idx] = fmaxf(fmaf(v, g_bn[scoff + c], g_bn[shoff + c]), 0.f);
}

// 3x3 conv 128->32 on BN'd planar feats, zero pad. Tile 32x32, 512 threads, 2 rows/thread.
__global__ void __launch_bounds__(512, 1) k_conv(const float* __restrict__ w_last) {
    __shared__ float s_in[8 * 1156];   // 8 channels x 34x34
    __shared__ float s_wc[2304];       // [c(8)][k(9)][o(32)]
    int tid = threadIdx.x;
    int tx = tid & 31, tyq = tid >> 5;   // tx col 0..31, tyq 0..15
    int gx0 = blockIdx.x * 32, gy0 = blockIdx.y * 32, b = blockIdx.z;
    const float* fb = g_feats + (size_t)b * CCAT * HWC;

    float acc0[32], acc1[32];
#pragma unroll
    for (int o = 0; o < 32; o++) { acc0[o] = 0.f; acc1[o] = 0.f; }

#pragma unroll 1
    for (int chunk = 0; chunk < 16; chunk++) {
        int c0 = chunk * 8;
        __syncthreads();
        for (int t = tid; t < 2304; t += 512) {
            int o = t & 31;
            int ck = t >> 5;                    // c*9+k, 0..71
            int c = ck / 9, k = ck - c * 9;
            s_wc[t] = w_last[(size_t)o * 1152 + (size_t)(c0 + c) * 9 + k];
        }
        for (int t = tid; t < 9248; t += 512) {
            int ch = t / 1156, pix = t - ch * 1156;
            int i = pix / 34, j = pix - i * 34;
            int gy = gy0 + i - 1, gx = gx0 + j - 1;
            float v = 0.f;
            if ((unsigned)gy < HH && (unsigned)gx < WW)
                v = fb[(size_t)(c0 + ch) * HWC + gy * WW + gx];
            s_in[t] = v;
        }
        __syncthreads();

#pragma unroll 1
        for (int c = 0; c < 8; c++) {
#pragma unroll
            for (int k = 0; k < 9; k++) {
                int ky = k / 3, kx = k - ky * 3;
                float v0 = s_in[c * 1156 + (tyq + ky) * 34 + tx + kx];
                float v1 = s_in[c * 1156 + (tyq + 16 + ky) * 34 + tx + kx];
                const float* wp = &s_wc[(c * 9 + k) * 32];
#pragma unroll
                for (int o = 0; o < 32; o++) {
                    float w = wp[o];
                    acc0[o] = fmaf(v0, w, acc0[o]);
                    acc1[o] = fmaf(v1, w, acc1[o]);
                }
            }
        }
    }

    {
        int gy = gy0 + tyq, gx = gx0 + tx;
        float* hp = g_h + (size_t)b * SFC * HWC + gy * WW + gx;
#pragma unroll
        for (int o = 0; o < 32; o++) hp[(size_t)o * HWC] = acc0[o];
    }
    {
        int gy = gy0 + tyq + 16, gx = gx0 + tx;
        float* hp = g_h + (size_t)b * SFC * HWC + gy * WW + gx;
#pragma unroll
        for (int o = 0; o < 32; o++) hp[(size_t)o * HWC] = acc1[o];
    }
}

// final 1x1: out[b,o,p] = sum_c h_bn[b,c,p] * w_final[o,c]
__global__ void k_final(const float* __restrict__ wf, float* __restrict__ out) {
    __shared__ float s_wf[1024];   // [o*32+c], source layout
    int tid = threadIdx.x;
#pragma unroll
    for (int it = 0; it < 4; it++) s_wf[tid + it * 256] = wf[tid + it * 256];
    __syncthreads();

    int idx = blockIdx.x * 256 + tid;
    int b = idx / HWC, p = idx - b * HWC;
    const float* hb = g_h + (size_t)b * SFC * HWC + p;
    float y[32];
#pragma unroll
    for (int c = 0; c < 32; c++) y[c] = hb[(size_t)c * HWC];
    float* op = out + (size_t)b * SFC * HWC + p;
#pragma unroll
    for (int o = 0; o < 32; o++) {
        float s = 0.f;
#pragma unroll
        for (int c = 0; c < 32; c++) s += y[c] * s_wf[o * 32 + c];
        op[(size_t)o * HWC] = s;
    }
}

extern "C" void kernel_launch(void* const* d_in, const int* in_sizes, int n_in,
                              void* d_out, int out_size) {
    // resolve by size (robust); pairing branch keyed on whether input 0 is x
    const float* x = nullptr;
    const float* w_last = nullptr;
    const float* w_fin = nullptr;
    const float* wN[4] = {nullptr, nullptr, nullptr, nullptr};
    const float* s32[10];
    int nw = 0, ns = 0;
    const int XSZ = (int)((size_t)BB * CIN * HWC);
    for (int i = 0; i < n_in; i++) {
        int sz = in_sizes[i];
        const float* ptr = (const float*)d_in[i];
        if (sz == XSZ) x = ptr;
        else if (sz == 32 * 128 * 9) w_last = ptr;
        else if (sz == 32 * 32) w_fin = ptr;
        else if (sz == 32 * 8) { if (nw < 4) wN[nw++] = ptr; }
        else if (sz == 32) { if (ns < 10) s32[ns++] = ptr; }
    }
    const float *g1, *b1, *g2, *b2, *g3, *b3, *g4, *b4, *g_last, *b_last;
    if (in_sizes[0] == XSZ) {
        g1 = s32[0]; b1 = s32[1]; g2 = s32[2]; b2 = s32[3];
        g3 = s32[4]; b3 = s32[5]; g4 = s32[6]; b4 = s32[7];
        g_last = s32[8]; b_last = s32[9];
    } else {
        b1 = s32[0]; b2 = s32[1]; b3 = s32[2]; b4 = s32[3]; b_last = s32[4];
        g1 = s32[5]; g2 = s32[6]; g3 = s32[7]; g4 = s32[8]; g_last = s32[9];
    }
    float* out = (float*)d_out;

    k_zero<<<1, 512>>>();
    k_norm<<<NPIX / 256, 256>>>(x);
    k_aff<<<NPIX / 256, 256>>>(wN[0], wN[1], wN[2], wN[3]);
    k_stats<<<dim3(128, 25), 256>>>(0, 128, 0);
    k_bnfin128<<<1, 128>>>(g1, b1, g2, b2, g3, b3, g4, b4);
    k_bnapply<<<(int)(((size_t)NPIX * CCAT) / 256), 256>>>(0, 128, 0, 128);
    k_conv<<<dim3(WW / 32, HH / 32, BB), 512>>>(w_last);
    k_stats<<<dim3(32, 25), 256>>>(1, 32, 256);
    k_bnfin32<<<1, 32>>>(g_last, b_last);
    k_bnapply<<<(int)(((size_t)NPIX * SFC) / 256), 256>>>(1, 32, 256, 288);
    k_final<<<NPIX / 256, 256>>>(w_fin, out);
}

// round 5
// speedup vs baseline: 1.2169x; 1.2169x over previous
#include <cuda_runtime.h>
#include <cstdint>

#define BB   4
#define CIN  32
#define HH   320
#define WW   640
#define HWC  (HH*WW)
#define NPIX (BB*HWC)
#define CCAT 128
#define SFC  32

// scratch (planar NCHW everywhere)
__device__ float g_xn[(size_t)NPIX * CIN];
__device__ float g_feats[(size_t)NPIX * CCAT];
__device__ float g_h[(size_t)NPIX * SFC];
__device__ float g_stats[512];  // [0:128) sum feats, [128:256) sumsq feats, [256:288) sum h, [288:320) sumsq h
__device__ float g_bn[512];     // [0:128) scale feats, [128:256) shift feats, [256:288) scale h, [288:320) shift h

__device__ __forceinline__ unsigned long long dup2(float v) {
    unsigned long long r;
    asm("mov.b64 %0, {%1, %1};" : "=l"(r) : "f"(v));
    return r;
}
__device__ __forceinline__ unsigned long long ffma2(unsigned long long a, unsigned long long b,
                                                    unsigned long long c) {
    unsigned long long d;
    asm("fma.rn.f32x2 %0, %1, %2, %3;" : "=l"(d) : "l"(a), "l"(b), "l"(c));
    return d;
}
__device__ __forceinline__ void unpack2(unsigned long long v, float& lo, float& hi) {
    asm("mov.b64 {%0, %1}, %2;" : "=f"(lo), "=f"(hi) : "l"(v));
}

__global__ void k_zero() { g_stats[threadIdx.x] = 0.f; }

// L2-normalize per pixel across channels (planar in, planar out)
__global__ void k_norm(const float* __restrict__ x) {
    int idx = blockIdx.x * 256 + threadIdx.x;
    int b = idx / HWC, p = idx - b * HWC;
    const float* xp = x + (size_t)b * CIN * HWC + p;
    float* op = g_xn + (size_t)b * CIN * HWC + p;
    float v[CIN];
    float ss = 0.f;
#pragma unroll
    for (int c = 0; c < CIN; c++) { v[c] = xp[(size_t)c * HWC]; ss += v[c] * v[c]; }
    float rn = 1.f / fmaxf(sqrtf(ss), 1e-12f);
#pragma unroll
    for (int c = 0; c < CIN; c++) op[(size_t)c * HWC] = v[c] * rn;
}

// affinity (4 dilations x 8 neighbors, unfold order) + per-branch 1x1 (8->32), planar out
__global__ void k_aff(const float* __restrict__ w1, const float* __restrict__ w2,
                      const float* __restrict__ w3, const float* __restrict__ w4) {
    __shared__ float s_w[4 * 256];   // [di][o*8+k], same layout as source
    {
        int tid = threadIdx.x;
        const float* ws[4] = {w1, w2, w3, w4};
        for (int di = 0; di < 4; di++) s_w[di * 256 + tid] = ws[di][tid];
    }
    __syncthreads();

    int idx = blockIdx.x * 256 + threadIdx.x;
    int b = idx / HWC, p = idx - b * HWC;
    int y = p / WW, xx = p - y * WW;
    const float* xb = g_xn + (size_t)b * CIN * HWC;

    float cv[CIN];
#pragma unroll
    for (int c = 0; c < CIN; c++) cv[c] = xb[(size_t)c * HWC + p];

#pragma unroll 1
    for (int di = 0; di < 4; di++) {
        int d = 1 << di;
        float a[8];
        int kk = 0;
#pragma unroll
        for (int iy = -1; iy <= 1; iy++) {
#pragma unroll
            for (int jx = -1; jx <= 1; jx++) {
                if (iy == 0 && jx == 0) continue;
                int ny = y + iy * d, nx = xx + jx * d;
                float dot = 0.f;
                if ((unsigned)ny < HH && (unsigned)nx < WW) {
                    int np = ny * WW + nx;
#pragma unroll
                    for (int c = 0; c < CIN; c++) dot += cv[c] * xb[(size_t)c * HWC + np];
                }
                a[kk++] = fmaxf(dot, 0.f);
            }
        }
        float* fo = g_feats + ((size_t)b * CCAT + di * 32) * HWC + p;
        const float* wd = &s_w[di * 256];
#pragma unroll
        for (int o = 0; o < 32; o++) {
            float s = 0.f;
#pragma unroll
            for (int k = 0; k < 8; k++) s += a[k] * wd[o * 8 + k];
            fo[(size_t)o * HWC] = s;
        }
    }
}

// per-channel sum & sumsq over planar buffer. which: 0 = g_feats(128ch), 1 = g_h(32ch)
__global__ void k_stats(int which, int nch, int statoff) {
    const float* buf = which ? g_h : g_feats;
    int c = blockIdx.x;
    int slice = blockIdx.y;      // 25 slices of 32768 elements over 4*HWC
    int tid = threadIdx.x;
    float s = 0.f, q = 0.f;
    int e0 = slice * 32768;
    for (int e = e0 + tid; e < e0 + 32768; e += 256) {
        int b = e / HWC, p = e - b * HWC;
        float v = buf[((size_t)b * nch + c) * HWC + p];
        s += v; q += v * v;
    }
    __shared__ float ss[256], sq[256];
    ss[tid] = s; sq[tid] = q;
    __syncthreads();
    for (int off = 128; off > 0; off >>= 1) {
        if (tid < off) { ss[tid] += ss[tid + off]; sq[tid] += sq[tid + off]; }
        __syncthreads();
    }
    if (tid == 0) {
        atomicAdd(&g_stats[statoff + c], ss[0]);
        atomicAdd(&g_stats[statoff + nch + c], sq[0]);
    }
}

__global__ void k_bnfin128(const float* __restrict__ g1, const float* __restrict__ b1,
                           const float* __restrict__ g2, const float* __restrict__ b2,
                           const float* __restrict__ g3, const float* __restrict__ b3,
                           const float* __restrict__ g4, const float* __restrict__ b4) {
    int c = threadIdx.x;
    float inv = 1.0f / (float)NPIX;
    float mean = g_stats[c] * inv;
    float var = g_stats[128 + c] * inv - mean * mean;
    int di = c >> 5, o = c & 31;
    const float* gs[4] = {g1, g2, g3, g4};
    const float* bs[4] = {b1, b2, b3, b4};
    float sc = gs[di][o] * rsqrtf(fmaxf(var, 0.f) + 1e-5f);
    g_bn[c] = sc;
    g_bn[128 + c] = bs[di][o] - mean * sc;
}

__global__ void k_bnfin32(const float* __restrict__ gl, const float* __restrict__ bl) {
    int o = threadIdx.x;
    float inv = 1.0f / (float)NPIX;
    float mean = g_stats[256 + o] * inv;
    float var = g_stats[288 + o] * inv - mean * mean;
    float sc = gl[o] * rsqrtf(fmaxf(var, 0.f) + 1e-5f);
    g_bn[256 + o] = sc;
    g_bn[288 + o] = bl[o] - mean * sc;
}

// 3x3 conv 128->32 on planar feats with BN+ReLU fused on load; f32x2 packed FMA.
// Tile 32x32, 512 threads, 2 rows/thread. Writes raw (pre-BN) h.
__global__ void __launch_bounds__(512, 1) k_conv(const float* __restrict__ w_last) {
    __shared__ float s_in[8 * 1156];                // 8 channels x 34x34
    __shared__ unsigned long long s_w[1152];        // [c(8)*9+k][o2(16)] packed o-pairs
    int tid = threadIdx.x;
    int tx = tid & 31, tyq = tid >> 5;   // col 0..31, row 0..15
    int gx0 = blockIdx.x * 32, gy0 = blockIdx.y * 32, b = blockIdx.z;
    const float* fb = g_feats + (size_t)b * CCAT * HWC;

    unsigned long long acc0[16], acc1[16];
#pragma unroll
    for (int o2 = 0; o2 < 16; o2++) { acc0[o2] = 0ull; acc1[o2] = 0ull; }

#pragma unroll 1
    for (int chunk = 0; chunk < 16; chunk++) {
        int c0 = chunk * 8;
        __syncthreads();
        // pack weights: [ck][o2] <- (w_last[2*o2][c0+c][k], w_last[2*o2+1][c0+c][k])
        for (int t = tid; t < 1152; t += 512) {
            int o2 = t & 15, ck = t >> 4;          // ck = c*9+k, 0..71
            int c = ck / 9, k = ck - c * 9;
            float lo = w_last[(size_t)(2 * o2) * 1152 + (size_t)(c0 + c) * 9 + k];
            float hi = w_last[(size_t)(2 * o2 + 1) * 1152 + (size_t)(c0 + c) * 9 + k];
            s_w[t] = (unsigned long long)__float_as_uint(lo) |
                     ((unsigned long long)__float_as_uint(hi) << 32);
        }
        // input tile with BN+ReLU fused
        for (int t = tid; t < 9248; t += 512) {
            int ch = t / 1156, pix = t - ch * 1156;
            int i = pix / 34, j = pix - i * 34;
            int gy = gy0 + i - 1, gx = gx0 + j - 1;
            float v = 0.f;
            if ((unsigned)gy < HH && (unsigned)gx < WW) {
                float raw = fb[(size_t)(c0 + ch) * HWC + gy * WW + gx];
                v = fmaxf(fmaf(raw, g_bn[c0 + ch], g_bn[128 + c0 + ch]), 0.f);
            }
            s_in[t] = v;
        }
        __syncthreads();

#pragma unroll 1
        for (int c = 0; c < 8; c++) {
#pragma unroll
            for (int k = 0; k < 9; k++) {
                int ky = k / 3, kx = k - ky * 3;
                unsigned long long wr[16];
                const unsigned long long* wp = &s_w[(c * 9 + k) * 16];
#pragma unroll
                for (int o2 = 0; o2 < 16; o2++) wr[o2] = wp[o2];
                unsigned long long vv0 = dup2(s_in[c * 1156 + (tyq + ky) * 34 + tx + kx]);
                unsigned long long vv1 = dup2(s_in[c * 1156 + (tyq + 16 + ky) * 34 + tx + kx]);
#pragma unroll
                for (int o2 = 0; o2 < 16; o2++) {
                    acc0[o2] = ffma2(vv0, wr[o2], acc0[o2]);
                    acc1[o2] = ffma2(vv1, wr[o2], acc1[o2]);
                }
            }
        }
    }

    {
        int gy = gy0 + tyq, gx = gx0 + tx;
        float* hp = g_h + (size_t)b * SFC * HWC + gy * WW + gx;
#pragma unroll
        for (int o2 = 0; o2 < 16; o2++) {
            float a0, a1;
            unpack2(acc0[o2], a0, a1);
            hp[(size_t)(2 * o2) * HWC] = a0;
            hp[(size_t)(2 * o2 + 1) * HWC] = a1;
        }
    }
    {
        int gy = gy0 + tyq + 16, gx = gx0 + tx;
        float* hp = g_h + (size_t)b * SFC * HWC + gy * WW + gx;
#pragma unroll
        for (int o2 = 0; o2 < 16; o2++) {
            float a0, a1;
            unpack2(acc1[o2], a0, a1);
            hp[(size_t)(2 * o2) * HWC] = a0;
            hp[(size_t)(2 * o2 + 1) * HWC] = a1;
        }
    }
}

// final 1x1 with BN+ReLU of h fused on load: out[b,o,p] = sum_c relu(bn(h))[c] * wf[o,c]
__global__ void k_final(const float* __restrict__ wf, float* __restrict__ out) {
    __shared__ float s_wf[1024];   // [o*32+c], source layout
    int tid = threadIdx.x;
#pragma unroll
    for (int it = 0; it < 4; it++) s_wf[tid + it * 256] = wf[tid + it * 256];
    __syncthreads();

    int idx = blockIdx.x * 256 + tid;
    int b = idx / HWC, p = idx - b * HWC;
    const float* hb = g_h + (size_t)b * SFC * HWC + p;
    float y[32];
#pragma unroll
    for (int c = 0; c < 32; c++) {
        float v = hb[(size_t)c * HWC];
        y[c] = fmaxf(fmaf(v, g_bn[256 + c], g_bn[288 + c]), 0.f);
    }
    float* op = out + (size_t)b * SFC * HWC + p;
#pragma unroll
    for (int o = 0; o < 32; o++) {
        float s = 0.f;
#pragma unroll
        for (int c = 0; c < 32; c++) s += y[c] * s_wf[o * 32 + c];
        op[(size_t)o * HWC] = s;
    }
}

extern "C" void kernel_launch(void* const* d_in, const int* in_sizes, int n_in,
                              void* d_out, int out_size) {
    const float* x = nullptr;
    const float* w_last = nullptr;
    const float* w_fin = nullptr;
    const float* wN[4] = {nullptr, nullptr, nullptr, nullptr};
    const float* s32[10];
    int nw = 0, ns = 0;
    const int XSZ = (int)((size_t)BB * CIN * HWC);
    for (int i = 0; i < n_in; i++) {
        int sz = in_sizes[i];
        const float* ptr = (const float*)d_in[i];
        if (sz == XSZ) x = ptr;
        else if (sz == 32 * 128 * 9) w_last = ptr;
        else if (sz == 32 * 32) w_fin = ptr;
        else if (sz == 32 * 8) { if (nw < 4) wN[nw++] = ptr; }
        else if (sz == 32) { if (ns < 10) s32[ns++] = ptr; }
    }
    const float *g1, *b1, *g2, *b2, *g3, *b3, *g4, *b4, *g_last, *b_last;
    if (in_sizes[0] == XSZ) {
        g1 = s32[0]; b1 = s32[1]; g2 = s32[2]; b2 = s32[3];
        g3 = s32[4]; b3 = s32[5]; g4 = s32[6]; b4 = s32[7];
        g_last = s32[8]; b_last = s32[9];
    } else {
        b1 = s32[0]; b2 = s32[1]; b3 = s32[2]; b4 = s32[3]; b_last = s32[4];
        g1 = s32[5]; g2 = s32[6]; g3 = s32[7]; g4 = s32[8]; g_last = s32[9];
    }
    float* out = (float*)d_out;

    k_zero<<<1, 512>>>();
    k_norm<<<NPIX / 256, 256>>>(x);
    k_aff<<<NPIX / 256, 256>>>(wN[0], wN[1], wN[2], wN[3]);
    k_stats<<<dim3(128, 25), 256>>>(0, 128, 0);
    k_bnfin128<<<1, 128>>>(g1, b1, g2, b2, g3, b3, g4, b4);
    k_conv<<<dim3(WW / 32, HH / 32, BB), 512>>>(w_last);
    k_stats<<<dim3(32, 25), 256>>>(1, 32, 256);
    k_bnfin32<<<1, 32>>>(g_last, b_last);
    k_final<<<NPIX / 256, 256>>>(w_fin, out);
}

// round 6
// speedup vs baseline: 1.2197x; 1.0023x over previous
#include <cuda_runtime.h>
#include <cstdint>

#define BB   4
#define CIN  32
#define HH   320
#define WW   640
#define HWC  (HH*WW)
#define NPIX (BB*HWC)
#define CCAT 128
#define SFC  32

// scratch (planar NCHW everywhere)
__device__ float g_xn[(size_t)NPIX * CIN];
__device__ float g_feats[(size_t)NPIX * CCAT];
__device__ float g_h[(size_t)NPIX * SFC];
__device__ float g_stats[512];
__device__ float g_bn[512];

__device__ __forceinline__ unsigned long long dup2(float v) {
    unsigned long long r;
    asm("mov.b64 %0, {%1, %1};" : "=l"(r) : "f"(v));
    return r;
}
__device__ __forceinline__ unsigned long long ffma2(unsigned long long a, unsigned long long b,
                                                    unsigned long long c) {
    unsigned long long d;
    asm("fma.rn.f32x2 %0, %1, %2, %3;" : "=l"(d) : "l"(a), "l"(b), "l"(c));
    return d;
}
__device__ __forceinline__ void unpack2(unsigned long long v, float& lo, float& hi) {
    asm("mov.b64 {%0, %1}, %2;" : "=f"(lo), "=f"(hi) : "l"(v));
}

__global__ void k_zero() { g_stats[threadIdx.x] = 0.f; }

__global__ void k_norm(const float* __restrict__ x) {
    int idx = blockIdx.x * 256 + threadIdx.x;
    int b = idx / HWC, p = idx - b * HWC;
    const float* xp = x + (size_t)b * CIN * HWC + p;
    float* op = g_xn + (size_t)b * CIN * HWC + p;
    float v[CIN];
    float ss = 0.f;
#pragma unroll
    for (int c = 0; c < CIN; c++) { v[c] = xp[(size_t)c * HWC]; ss += v[c] * v[c]; }
    float rn = 1.f / fmaxf(sqrtf(ss), 1e-12f);
#pragma unroll
    for (int c = 0; c < CIN; c++) op[(size_t)c * HWC] = v[c] * rn;
}

__global__ void k_aff(const float* __restrict__ w1, const float* __restrict__ w2,
                      const float* __restrict__ w3, const float* __restrict__ w4) {
    __shared__ float s_w[4 * 256];
    {
        int tid = threadIdx.x;
        const float* ws[4] = {w1, w2, w3, w4};
        for (int di = 0; di < 4; di++) s_w[di * 256 + tid] = ws[di][tid];
    }
    __syncthreads();

    int idx = blockIdx.x * 256 + threadIdx.x;
    int b = idx / HWC, p = idx - b * HWC;
    int y = p / WW, xx = p - y * WW;
    const float* xb = g_xn + (size_t)b * CIN * HWC;

    float cv[CIN];
#pragma unroll
    for (int c = 0; c < CIN; c++) cv[c] = xb[(size_t)c * HWC + p];

#pragma unroll 1
    for (int di = 0; di < 4; di++) {
        int d = 1 << di;
        float a[8];
        int kk = 0;
#pragma unroll
        for (int iy = -1; iy <= 1; iy++) {
#pragma unroll
            for (int jx = -1; jx <= 1; jx++) {
                if (iy == 0 && jx == 0) continue;
                int ny = y + iy * d, nx = xx + jx * d;
                float dot = 0.f;
                if ((unsigned)ny < HH && (unsigned)nx < WW) {
                    int np = ny * WW + nx;
#pragma unroll
                    for (int c = 0; c < CIN; c++) dot += cv[c] * xb[(size_t)c * HWC + np];
                }
                a[kk++] = fmaxf(dot, 0.f);
            }
        }
        float* fo = g_feats + ((size_t)b * CCAT + di * 32) * HWC + p;
        const float* wd = &s_w[di * 256];
#pragma unroll
        for (int o = 0; o < 32; o++) {
            float s = 0.f;
#pragma unroll
            for (int k = 0; k < 8; k++) s += a[k] * wd[o * 8 + k];
            fo[(size_t)o * HWC] = s;
        }
    }
}

// per-channel sum & sumsq, float4 vectorized. which: 0 = g_feats(128ch), 1 = g_h(32ch)
__global__ void k_stats(int which, int nch, int statoff) {
    const float* buf = which ? g_h : g_feats;
    int c = blockIdx.x;
    int slice = blockIdx.y;              // 25 slices of 8192 float4 over 4*HWC
    int tid = threadIdx.x;
    const int P4 = HWC / 4;              // float4s per (b,c) plane
    float s = 0.f, q = 0.f;
    int e0 = slice * 8192;
    for (int e = e0 + tid; e < e0 + 8192; e += 256) {
        int b = e / P4, p4 = e - b * P4;
        const float4* plane = reinterpret_cast<const float4*>(buf + ((size_t)b * nch + c) * HWC);
        float4 v = plane[p4];
        s += v.x + v.y + v.z + v.w;
        q += v.x * v.x + v.y * v.y + v.z * v.z + v.w * v.w;
    }
    __shared__ float ss[256], sq[256];
    ss[tid] = s; sq[tid] = q;
    __syncthreads();
    for (int off = 128; off > 0; off >>= 1) {
        if (tid < off) { ss[tid] += ss[tid + off]; sq[tid] += sq[tid + off]; }
        __syncthreads();
    }
    if (tid == 0) {
        atomicAdd(&g_stats[statoff + c], ss[0]);
        atomicAdd(&g_stats[statoff + nch + c], sq[0]);
    }
}

__global__ void k_bnfin128(const float* __restrict__ g1, const float* __restrict__ b1,
                           const float* __restrict__ g2, const float* __restrict__ b2,
                           const float* __restrict__ g3, const float* __restrict__ b3,
                           const float* __restrict__ g4, const float* __restrict__ b4) {
    int c = threadIdx.x;
    float inv = 1.0f / (float)NPIX;
    float mean = g_stats[c] * inv;
    float var = g_stats[128 + c] * inv - mean * mean;
    int di = c >> 5, o = c & 31;
    const float* gs[4] = {g1, g2, g3, g4};
    const float* bs[4] = {b1, b2, b3, b4};
    float sc = gs[di][o] * rsqrtf(fmaxf(var, 0.f) + 1e-5f);
    g_bn[c] = sc;
    g_bn[128 + c] = bs[di][o] - mean * sc;
}

__global__ void k_bnfin32(const float* __restrict__ gl, const float* __restrict__ bl) {
    int o = threadIdx.x;
    float inv = 1.0f / (float)NPIX;
    float mean = g_stats[256 + o] * inv;
    float var = g_stats[288 + o] * inv - mean * mean;
    float sc = gl[o] * rsqrtf(fmaxf(var, 0.f) + 1e-5f);
    g_bn[256 + o] = sc;
    g_bn[288 + o] = bl[o] - mean * sc;
}

// 3x3 conv 128->32, BN+ReLU fused on load, f32x2 FMA.
// 256 threads, 32x32 tile, 4 rows/thread (tyq, +8, +16, +24).
__global__ void __launch_bounds__(256, 1) k_conv(const float* __restrict__ w_last) {
    __shared__ float s_in[8 * 1156];                     // 8 ch x 34x34
    __shared__ __align__(16) unsigned long long s_w[1152]; // [(c*9+k)*16 + o2]
    int tid = threadIdx.x;
    int tx = tid & 31, tyq = tid >> 5;   // col 0..31, row 0..7
    int gx0 = blockIdx.x * 32, gy0 = blockIdx.y * 32, b = blockIdx.z;
    const float* fb = g_feats + (size_t)b * CCAT * HWC;

    unsigned long long acc[4][16];
#pragma unroll
    for (int px = 0; px < 4; px++)
#pragma unroll
        for (int o2 = 0; o2 < 16; o2++) acc[px][o2] = 0ull;

#pragma unroll 1
    for (int chunk = 0; chunk < 16; chunk++) {
        int c0 = chunk * 8;
        __syncthreads();
        for (int t = tid; t < 1152; t += 256) {
            int o2 = t & 15, ck = t >> 4;
            int c = ck / 9, k = ck - c * 9;
            float lo = w_last[(size_t)(2 * o2) * 1152 + (size_t)(c0 + c) * 9 + k];
            float hi = w_last[(size_t)(2 * o2 + 1) * 1152 + (size_t)(c0 + c) * 9 + k];
            s_w[t] = (unsigned long long)__float_as_uint(lo) |
                     ((unsigned long long)__float_as_uint(hi) << 32);
        }
        for (int t = tid; t < 9248; t += 256) {
            int ch = t / 1156, pix = t - ch * 1156;
            int i = pix / 34, j = pix - i * 34;
            int gy = gy0 + i - 1, gx = gx0 + j - 1;
            float v = 0.f;
            if ((unsigned)gy < HH && (unsigned)gx < WW) {
                float raw = fb[(size_t)(c0 + ch) * HWC + gy * WW + gx];
                v = fmaxf(fmaf(raw, g_bn[c0 + ch], g_bn[128 + c0 + ch]), 0.f);
            }
            s_in[t] = v;
        }
        __syncthreads();

#pragma unroll 1
        for (int c = 0; c < 8; c++) {
#pragma unroll
            for (int k = 0; k < 9; k++) {
                int ky = k / 3, kx = k - ky * 3;
                // weights: 8 x LDS.128
                ulonglong2 wr2[8];
                const ulonglong2* wp2 = reinterpret_cast<const ulonglong2*>(&s_w[(c * 9 + k) * 16]);
#pragma unroll
                for (int j = 0; j < 8; j++) wr2[j] = wp2[j];
                unsigned long long vv[4];
#pragma unroll
                for (int px = 0; px < 4; px++)
                    vv[px] = dup2(s_in[c * 1156 + (tyq + px * 8 + ky) * 34 + tx + kx]);
#pragma unroll
                for (int px = 0; px < 4; px++) {
#pragma unroll
                    for (int j = 0; j < 8; j++) {
                        acc[px][2 * j]     = ffma2(vv[px], wr2[j].x, acc[px][2 * j]);
                        acc[px][2 * j + 1] = ffma2(vv[px], wr2[j].y, acc[px][2 * j + 1]);
                    }
                }
            }
        }
    }

#pragma unroll
    for (int px = 0; px < 4; px++) {
        int gy = gy0 + tyq + px * 8, gx = gx0 + tx;
        float* hp = g_h + (size_t)b * SFC * HWC + gy * WW + gx;
#pragma unroll
        for (int o2 = 0; o2 < 16; o2++) {
            float a0, a1;
            unpack2(acc[px][o2], a0, a1);
            hp[(size_t)(2 * o2) * HWC] = a0;
            hp[(size_t)(2 * o2 + 1) * HWC] = a1;
        }
    }
}

__global__ void k_final(const float* __restrict__ wf, float* __restrict__ out) {
    __shared__ float s_wf[1024];
    int tid = threadIdx.x;
#pragma unroll
    for (int it = 0; it < 4; it++) s_wf[tid + it * 256] = wf[tid + it * 256];
    __syncthreads();

    int idx = blockIdx.x * 256 + tid;
    int b = idx / HWC, p = idx - b * HWC;
    const float* hb = g_h + (size_t)b * SFC * HWC + p;
    float y[32];
#pragma unroll
    for (int c = 0; c < 32; c++) {
        float v = hb[(size_t)c * HWC];
        y[c] = fmaxf(fmaf(v, g_bn[256 + c], g_bn[288 + c]), 0.f);
    }
    float* op = out + (size_t)b * SFC * HWC + p;
#pragma unroll
    for (int o = 0; o < 32; o++) {
        float s = 0.f;
#pragma unroll
        for (int c = 0; c < 32; c++) s += y[c] * s_wf[o * 32 + c];
        op[(size_t)o * HWC] = s;
    }
}

extern "C" void kernel_launch(void* const* d_in, const int* in_sizes, int n_in,
                              void* d_out, int out_size) {
    const float* x = nullptr;
    const float* w_last = nullptr;
    const float* w_fin = nullptr;
    const float* wN[4] = {nullptr, nullptr, nullptr, nullptr};
    const float* s32[10];
    int nw = 0, ns = 0;
    const int XSZ = (int)((size_t)BB * CIN * HWC);
    for (int i = 0; i < n_in; i++) {
        int sz = in_sizes[i];
        const float* ptr = (const float*)d_in[i];
        if (sz == XSZ) x = ptr;
        else if (sz == 32 * 128 * 9) w_last = ptr;
        else if (sz == 32 * 32) w_fin = ptr;
        else if (sz == 32 * 8) { if (nw < 4) wN[nw++] = ptr; }
        else if (sz == 32) { if (ns < 10) s32[ns++] = ptr; }
    }
    const float *g1, *b1, *g2, *b2, *g3, *b3, *g4, *b4, *g_last, *b_last;
    if (in_sizes[0] == XSZ) {
        g1 = s32[0]; b1 = s32[1]; g2 = s32[2]; b2 = s32[3];
        g3 = s32[4]; b3 = s32[5]; g4 = s32[6]; b4 = s32[7];
        g_last = s32[8]; b_last = s32[9];
    } else {
        b1 = s32[0]; b2 = s32[1]; b3 = s32[2]; b4 = s32[3]; b_last = s32[4];
        g1 = s32[5]; g2 = s32[6]; g3 = s32[7]; g4 = s32[8]; g_last = s32[9];
    }
    float* out = (float*)d_out;

    k_zero<<<1, 512>>>();
    k_norm<<<NPIX / 256, 256>>>(x);
    k_aff<<<NPIX / 256, 256>>>(wN[0], wN[1], wN[2], wN[3]);
    k_stats<<<dim3(128, 25), 256>>>(0, 128, 0);
    k_bnfin128<<<1, 128>>>(g1, b1, g2, b2, g3, b3, g4, b4);
    k_conv<<<dim3(WW / 32, HH / 32, BB), 256>>>(w_last);
    k_stats<<<dim3(32, 25), 256>>>(1, 32, 256);
    k_bnfin32<<<1, 32>>>(g_last, b_last);
    k_final<<<NPIX / 256, 256>>>(w_fin, out);
}

// round 8
// speedup vs baseline: 2.1468x; 1.7602x over previous
#include <cuda_runtime.h>
#include <cuda_bf16.h>
#include <cstdint>

#define BB   4
#define CIN  32
#define HH   320
#define WW   640
#define HWC  (HH*WW)
#define NPIX (BB*HWC)
#define CCAT 128
#define SFC  32

// ---------------- device scratch ----------------
__device__ float g_xn[(size_t)NPIX * CIN];
__device__ float g_feats[(size_t)NPIX * CCAT];                      // planar pre-BN
__device__ __align__(256) unsigned int g_fbf[(size_t)NPIX * CCAT];  // [chunk4][pix][32 u32: hi16|lo16]
__device__ float g_h[(size_t)NPIX * SFC];                           // planar pre-BN
__device__ __align__(128) unsigned int g_wm[36864];                 // mma-fragment-ordered weights
__device__ float g_stats[512];
__device__ float g_bn[512];

__device__ __forceinline__ uint32_t smem_u32(const void* p) {
    uint32_t a;
    asm("{ .reg .u64 t; cvta.to.shared.u64 t, %1; cvt.u32.u64 %0, t; }" : "=r"(a) : "l"(p));
    return a;
}
#define MMA16816(c, a, b0v, b1v) \
    asm volatile("mma.sync.aligned.m16n8k16.row.col.f32.bf16.bf16.f32 " \
                 "{%0,%1,%2,%3},{%4,%5,%6,%7},{%8,%9},{%0,%1,%2,%3};" \
                 : "+f"((c)[0]), "+f"((c)[1]), "+f"((c)[2]), "+f"((c)[3]) \
                 : "r"((a)[0]), "r"((a)[1]), "r"((a)[2]), "r"((a)[3]), "r"(b0v), "r"(b1v))

// ---------------- validated kernels (unchanged) ----------------
__global__ void k_zero() { g_stats[threadIdx.x] = 0.f; }

__global__ void k_norm(const float* __restrict__ x) {
    int idx = blockIdx.x * 256 + threadIdx.x;
    int b = idx / HWC, p = idx - b * HWC;
    const float* xp = x + (size_t)b * CIN * HWC + p;
    float* op = g_xn + (size_t)b * CIN * HWC + p;
    float v[CIN]; float ss = 0.f;
#pragma unroll
    for (int c = 0; c < CIN; c++) { v[c] = xp[(size_t)c * HWC]; ss += v[c] * v[c]; }
    float rn = 1.f / fmaxf(sqrtf(ss), 1e-12f);
#pragma unroll
    for (int c = 0; c < CIN; c++) op[(size_t)c * HWC] = v[c] * rn;
}

__global__ void k_aff(const float* __restrict__ w1, const float* __restrict__ w2,
                      const float* __restrict__ w3, const float* __restrict__ w4) {
    __shared__ float s_w[4 * 256];
    {
        int tid = threadIdx.x;
        const float* ws[4] = {w1, w2, w3, w4};
        for (int di = 0; di < 4; di++) s_w[di * 256 + tid] = ws[di][tid];
    }
    __syncthreads();
    int idx = blockIdx.x * 256 + threadIdx.x;
    int b = idx / HWC, p = idx - b * HWC;
    int y = p / WW, xx = p - y * WW;
    const float* xb = g_xn + (size_t)b * CIN * HWC;
    float cv[CIN];
#pragma unroll
    for (int c = 0; c < CIN; c++) cv[c] = xb[(size_t)c * HWC + p];
#pragma unroll 1
    for (int di = 0; di < 4; di++) {
        int d = 1 << di;
        float a[8]; int kk = 0;
#pragma unroll
        for (int iy = -1; iy <= 1; iy++)
#pragma unroll
            for (int jx = -1; jx <= 1; jx++) {
                if (iy == 0 && jx == 0) continue;
                int ny = y + iy * d, nx = xx + jx * d;
                float dot = 0.f;
                if ((unsigned)ny < HH && (unsigned)nx < WW) {
                    int np = ny * WW + nx;
#pragma unroll
                    for (int c = 0; c < CIN; c++) dot += cv[c] * xb[(size_t)c * HWC + np];
                }
                a[kk++] = fmaxf(dot, 0.f);
            }
        float* fo = g_feats + ((size_t)b * CCAT + di * 32) * HWC + p;
        const float* wd = &s_w[di * 256];
#pragma unroll
        for (int o = 0; o < 32; o++) {
            float s = 0.f;
#pragma unroll
            for (int k = 0; k < 8; k++) s += a[k] * wd[o * 8 + k];
            fo[(size_t)o * HWC] = s;
        }
    }
}

__global__ void k_stats(int which, int nch, int statoff) {
    const float* buf = which ? g_h : g_feats;
    int c = blockIdx.x, slice = blockIdx.y, tid = threadIdx.x;
    const int P4 = HWC / 4;
    float s = 0.f, q = 0.f;
    int e0 = slice * 8192;
    for (int e = e0 + tid; e < e0 + 8192; e += 256) {
        int b = e / P4, p4 = e - b * P4;
        const float4* plane = reinterpret_cast<const float4*>(buf + ((size_t)b * nch + c) * HWC);
        float4 v = plane[p4];
        s += v.x + v.y + v.z + v.w;
        q += v.x * v.x + v.y * v.y + v.z * v.z + v.w * v.w;
    }
    __shared__ float ss[256], sq[256];
    ss[tid] = s; sq[tid] = q;
    __syncthreads();
    for (int off = 128; off > 0; off >>= 1) {
        if (tid < off) { ss[tid] += ss[tid + off]; sq[tid] += sq[tid + off]; }
        __syncthreads();
    }
    if (tid == 0) {
        atomicAdd(&g_stats[statoff + c], ss[0]);
        atomicAdd(&g_stats[statoff + nch + c], sq[0]);
    }
}

__global__ void k_bnfin128(const float* __restrict__ g1, const float* __restrict__ b1,
                           const float* __restrict__ g2, const float* __restrict__ b2,
                           const float* __restrict__ g3, const float* __restrict__ b3,
                           const float* __restrict__ g4, const float* __restrict__ b4) {
    int c = threadIdx.x;
    float inv = 1.0f / (float)NPIX;
    float mean = g_stats[c] * inv;
    float var = g_stats[128 + c] * inv - mean * mean;
    int di = c >> 5, o = c & 31;
    const float* gs[4] = {g1, g2, g3, g4};
    const float* bs[4] = {b1, b2, b3, b4};
    float sc = gs[di][o] * rsqrtf(fmaxf(var, 0.f) + 1e-5f);
    g_bn[c] = sc;
    g_bn[128 + c] = bs[di][o] - mean * sc;
}

__global__ void k_bnfin32(const float* __restrict__ gl, const float* __restrict__ bl) {
    int o = threadIdx.x;
    float inv = 1.0f / (float)NPIX;
    float mean = g_stats[256 + o] * inv;
    float var = g_stats[288 + o] * inv - mean * mean;
    float sc = gl[o] * rsqrtf(fmaxf(var, 0.f) + 1e-5f);
    g_bn[256 + o] = sc;
    g_bn[288 + o] = bl[o] - mean * sc;
}

__global__ void k_final(const float* __restrict__ wf, float* __restrict__ out) {
    __shared__ float s_wf[1024];
    int tid = threadIdx.x;
#pragma unroll
    for (int it = 0; it < 4; it++) s_wf[tid + it * 256] = wf[tid + it * 256];
    __syncthreads();
    int idx = blockIdx.x * 256 + tid;
    int b = idx / HWC, p = idx - b * HWC;
    const float* hb = g_h + (size_t)b * SFC * HWC + p;
    float y[32];
#pragma unroll
    for (int c = 0; c < 32; c++) {
        float v = hb[(size_t)c * HWC];
        y[c] = fmaxf(fmaf(v, g_bn[256 + c], g_bn[288 + c]), 0.f);
    }
    float* op = out + (size_t)b * SFC * HWC + p;
#pragma unroll
    for (int o = 0; o < 32; o++) {
        float s = 0.f;
#pragma unroll
        for (int c = 0; c < 32; c++) s += y[c] * s_wf[o * 32 + c];
        op[(size_t)o * HWC] = s;
    }
}

// ---------------- BN+ReLU + fp32->bf16(hi/lo), chunk-major pixel rows ----------------
__global__ void k_bncvt() {
    __shared__ float s_t[128][65];
    int tid = threadIdx.x;
    int p0 = blockIdx.x * 64;
    int b = p0 / HWC, poff = p0 - b * HWC;
    {
        int c_sub = tid >> 6, p_l = tid & 63;
        for (int c = c_sub; c < 128; c += 4)
            s_t[c][p_l] = g_feats[((size_t)b * CCAT + c) * HWC + poff + p_l];
    }
    __syncthreads();
    int j = tid & 31, p_sub = tid >> 5;
    bool is_lo = (j >= 16);
    int jj = is_lo ? (j - 16) : j;
    for (int p_l = p_sub; p_l < 64; p_l += 8) {
#pragma unroll
        for (int chunk = 0; chunk < 4; chunk++) {
            int ch = chunk * 32 + 2 * jj;
            float v0 = fmaxf(fmaf(s_t[ch][p_l],     g_bn[ch],     g_bn[128 + ch]),     0.f);
            float v1 = fmaxf(fmaf(s_t[ch + 1][p_l], g_bn[ch + 1], g_bn[128 + ch + 1]), 0.f);
            __nv_bfloat16 h0 = __float2bfloat16_rn(v0);
            __nv_bfloat16 h1 = __float2bfloat16_rn(v1);
            unsigned short u0, u1;
            if (is_lo) {
                u0 = __bfloat16_as_ushort(__float2bfloat16_rn(v0 - __bfloat162float(h0)));
                u1 = __bfloat16_as_ushort(__float2bfloat16_rn(v1 - __bfloat162float(h1)));
            } else {
                u0 = __bfloat16_as_ushort(h0);
                u1 = __bfloat16_as_ushort(h1);
            }
            g_fbf[((size_t)chunk * NPIX + p0 + p_l) * 32 + j] = (uint32_t)u0 | ((uint32_t)u1 << 16);
        }
    }
}

// ---------------- weight prep: mma B-fragment order, bf16 hi/lo ----------------
// linear u32 index u = (ky*4+chunk)*3072 + ((kx*4+s)*4+nt)*64 + l*2 + r
__global__ void k_wprep2(const float* __restrict__ w_last) {
    int u = blockIdx.x * 256 + threadIdx.x;   // < 36864
    int tile = u / 3072;
    int ky = tile >> 2, chunk = tile & 3;
    int rem = u - tile * 3072;
    int idx = rem >> 6;
    int lr = rem & 63;
    int l = lr >> 1, r = lr & 1;
    int kx = idx >> 4;
    int s = (idx >> 2) & 3;
    int nt = idx & 3;
    int gid = l >> 2, tid4 = l & 3;
    int o = nt * 8 + gid;
    int kloc = 2 * tid4 + r * 8;
    int c0 = chunk * 32 + (s & 1) * 16 + kloc;
    int tap = ky * 3 + kx;
    float w0 = w_last[o * 1152 + c0 * 9 + tap];
    float w1 = w_last[o * 1152 + (c0 + 1) * 9 + tap];
    unsigned short q0, q1;
    if (s < 2) {
        q0 = __bfloat16_as_ushort(__float2bfloat16_rn(w0));
        q1 = __bfloat16_as_ushort(__float2bfloat16_rn(w1));
    } else {
        __nv_bfloat16 h0 = __float2bfloat16_rn(w0), h1 = __float2bfloat16_rn(w1);
        q0 = __bfloat16_as_ushort(__float2bfloat16_rn(w0 - __bfloat162float(h0)));
        q1 = __bfloat16_as_ushort(__float2bfloat16_rn(w1 - __bfloat162float(h1)));
    }
    g_wm[u] = (uint32_t)q0 | ((uint32_t)q1 << 16);
}

// ---------------- HMMA conv: 128 px strip x 96 (3 kx-groups x 32 o), K=3ky x 4chunk x 96eff ----------------
// smem: 2 stages of (A 128x144B = 18432) + (B 12288) = 30720 each; epilogue S[128][100] f32 aliases stage0.
#define STG_BYTES 30720
#define SMEM_CONV (2 * STG_BYTES)

__global__ void __launch_bounds__(128) k_convmma2() {
    extern __shared__ __align__(16) char smem[];
    const uint32_t sbase = smem_u32(smem);
    int tid = threadIdx.x;
    int warp = tid >> 5, lane = tid & 31;
    int gid = lane >> 2, tid4 = lane & 3;
    int x0 = blockIdx.x * 126 - 1;
    int gy = blockIdx.y, b = blockIdx.z;

    float acc[2][12][4];
#pragma unroll
    for (int mt = 0; mt < 2; mt++)
#pragma unroll
        for (int n = 0; n < 12; n++)
#pragma unroll
            for (int e = 0; e < 4; e++) acc[mt][n][e] = 0.f;

#define LOAD_TILE(I) do { \
    int _ky = (I) >> 2, _ck = (I) & 3, _st = (I) & 1; \
    uint32_t _ab = sbase + _st * STG_BYTES; \
    uint32_t _bb = _ab + 18432; \
    int _yy = gy + _ky - 1; \
    int _gx = x0 + tid; \
    bool _ok = ((unsigned)_yy < HH) && ((unsigned)_gx < WW); \
    size_t _pix = (size_t)b * HWC + (size_t)(_ok ? _yy : 0) * WW + (_ok ? _gx : 0); \
    const char* _src = (const char*)g_fbf + ((size_t)_ck * NPIX + _pix) * 128; \
    uint32_t _dst = _ab + tid * 144; \
    int _sz = _ok ? 16 : 0; \
    _Pragma("unroll") \
    for (int _j = 0; _j < 8; _j++) \
        asm volatile("cp.async.cg.shared.global [%0], [%1], 16, %2;" \
                     :: "r"(_dst + _j * 16), "l"(_src + _j * 16), "r"(_sz)); \
    const char* _ws = (const char*)g_wm + (size_t)(I) * 12288; \
    _Pragma("unroll") \
    for (int _j = 0; _j < 6; _j++) { \
        int _off = (tid + _j * 128) * 16; \
        asm volatile("cp.async.cg.shared.global [%0], [%1], 16, 16;" \
                     :: "r"(_bb + _off), "l"(_ws + _off)); \
    } \
    asm volatile("cp.async.commit_group;"); \
} while (0)

    LOAD_TILE(0);

#pragma unroll 1
    for (int i = 0; i < 12; i++) {
        if (i + 1 < 12) {
            LOAD_TILE(i + 1);
            asm volatile("cp.async.wait_group 1;");
        } else {
            asm volatile("cp.async.wait_group 0;");
        }
        __syncthreads();
        int st = i & 1;
        const uint32_t* As = reinterpret_cast<const uint32_t*>(smem + st * STG_BYTES);
        const char* Bs = smem + st * STG_BYTES + 18432;

        uint32_t ar[4][2][4];
        {
            int r0 = warp * 32 + gid;
#pragma unroll
            for (int q = 0; q < 4; q++)
#pragma unroll
                for (int mt = 0; mt < 2; mt++) {
                    int row = r0 + mt * 16;
                    ar[q][mt][0] = As[row * 36 + q * 8 + tid4];
                    ar[q][mt][1] = As[(row + 8) * 36 + q * 8 + tid4];
                    ar[q][mt][2] = As[row * 36 + q * 8 + 4 + tid4];
                    ar[q][mt][3] = As[(row + 8) * 36 + q * 8 + 4 + tid4];
                }
        }
#pragma unroll
        for (int kx = 0; kx < 3; kx++) {
            uint32_t bw[4][4][2];
#pragma unroll
            for (int s = 0; s < 4; s++)
#pragma unroll
                for (int nt = 0; nt < 4; nt++) {
                    unsigned long long v = *reinterpret_cast<const unsigned long long*>(
                        Bs + ((kx * 4 + s) * 4 + nt) * 256 + lane * 8);
                    bw[s][nt][0] = (uint32_t)v;
                    bw[s][nt][1] = (uint32_t)(v >> 32);
                }
            // pass pairs (A-slice q, B-kset s): (0,0)(1,1)(0,2)(1,3)(2,0)(3,1)
#pragma unroll
            for (int mt = 0; mt < 2; mt++)
#pragma unroll
                for (int nt = 0; nt < 4; nt++) {
                    float* c = acc[mt][kx * 4 + nt];
                    MMA16816(c, ar[0][mt], bw[0][nt][0], bw[0][nt][1]);
                    MMA16816(c, ar[1][mt], bw[1][nt][0], bw[1][nt][1]);
                    MMA16816(c, ar[0][mt], bw[2][nt][0], bw[2][nt][1]);
                    MMA16816(c, ar[1][mt], bw[3][nt][0], bw[3][nt][1]);
                    MMA16816(c, ar[2][mt], bw[0][nt][0], bw[0][nt][1]);
                    MMA16816(c, ar[3][mt], bw[1][nt][0], bw[1][nt][1]);
                }
        }
        __syncthreads();
    }

    // epilogue: stage accumulators to smem, combine kx groups with +/-1 pixel shift
    float* S = reinterpret_cast<float*>(smem);
#pragma unroll
    for (int mt = 0; mt < 2; mt++)
#pragma unroll
        for (int ng = 0; ng < 12; ng++) {
            int row = warp * 32 + mt * 16 + gid;
            int col = ng * 8 + tid4 * 2;
            S[row * 100 + col]         = acc[mt][ng][0];
            S[row * 100 + col + 1]     = acc[mt][ng][1];
            S[(row + 8) * 100 + col]     = acc[mt][ng][2];
            S[(row + 8) * 100 + col + 1] = acc[mt][ng][3];
        }
    __syncthreads();

    int p = tid;
    int gx = x0 + p;
    if (p >= 1 && p <= 126 && gx < WW) {
        float* hp = g_h + (size_t)b * SFC * HWC + (size_t)gy * WW + gx;
#pragma unroll
        for (int o = 0; o < 32; o++) {
            float v = S[(p - 1) * 100 + o] + S[p * 100 + 32 + o] + S[(p + 1) * 100 + 64 + o];
            hp[(size_t)o * HWC] = v;
        }
    }
}

// ---------------- launcher ----------------
extern "C" void kernel_launch(void* const* d_in, const int* in_sizes, int n_in,
                              void* d_out, int out_size) {
    const float* x = nullptr;
    const float* w_last = nullptr;
    const float* w_fin = nullptr;
    const float* wN[4] = {nullptr, nullptr, nullptr, nullptr};
    const float* s32[10];
    int nw = 0, ns = 0;
    const int XSZ = (int)((size_t)BB * CIN * HWC);
    for (int i = 0; i < n_in; i++) {
        int sz = in_sizes[i];
        const float* ptr = (const float*)d_in[i];
        if (sz == XSZ) x = ptr;
        else if (sz == 32 * 128 * 9) w_last = ptr;
        else if (sz == 32 * 32) w_fin = ptr;
        else if (sz == 32 * 8) { if (nw < 4) wN[nw++] = ptr; }
        else if (sz == 32) { if (ns < 10) s32[ns++] = ptr; }
    }
    const float *g1, *b1, *g2, *b2, *g3, *b3, *g4, *b4, *g_last, *b_last;
    if (in_sizes[0] == XSZ) {
        g1 = s32[0]; b1 = s32[1]; g2 = s32[2]; b2 = s32[3];
        g3 = s32[4]; b3 = s32[5]; g4 = s32[6]; b4 = s32[7];
        g_last = s32[8]; b_last = s32[9];
    } else {
        b1 = s32[0]; b2 = s32[1]; b3 = s32[2]; b4 = s32[3]; b_last = s32[4];
        g1 = s32[5]; g2 = s32[6]; g3 = s32[7]; g4 = s32[8]; g_last = s32[9];
    }
    float* out = (float*)d_out;

    cudaFuncSetAttribute(k_convmma2, cudaFuncAttributeMaxDynamicSharedMemorySize, SMEM_CONV);

    k_zero<<<1, 512>>>();
    k_norm<<<NPIX / 256, 256>>>(x);
    k_aff<<<NPIX / 256, 256>>>(wN[0], wN[1], wN[2], wN[3]);
    k_stats<<<dim3(128, 25), 256>>>(0, 128, 0);
    k_bnfin128<<<1, 128>>>(g1, b1, g2, b2, g3, b3, g4, b4);
    k_bncvt<<<NPIX / 64, 256>>>();
    k_wprep2<<<144, 256>>>(w_last);
    k_convmma2<<<dim3(6, HH, BB), 128, SMEM_CONV>>>();
    k_stats<<<dim3(32, 25), 256>>>(1, 32, 256);
    k_bnfin32<<<1, 32>>>(g_last, b_last);
    k_final<<<NPIX / 256, 256>>>(w_fin, out);
}